// round 5
// baseline (speedup 1.0000x reference)
#include <cuda_runtime.h>
#include <math.h>

// Problem constants
#define NIMG 72                 // BATCH(8) * NUM_MODES(3) * NUM_WL(3)
#define H 512
#define IMG_ELEMS (H * H)       // 262144
#define NWL 3
#define NUM_LAYERS 5

// ---------------------------------------------------------------------------
// Scratch (no allocations allowed -> __device__ globals)
// ---------------------------------------------------------------------------
__device__ float2 g_bufA[NIMG * IMG_ELEMS];   // ~151 MB
__device__ float2 g_bufB[NIMG * IMG_ELEMS];   // ~151 MB
__device__ float2 g_PLT [NWL * IMG_ELEMS];    // prop_layer, stored TRANSPOSED: [w][b][a]
__device__ float2 g_PLDT[NWL * IMG_ELEMS];    // prop_layer * prop_det, transposed
__device__ float2 g_tw[512];                  // forward twiddles exp(-2*pi*i*k/512)

// ---------------------------------------------------------------------------
// Complex helpers
// ---------------------------------------------------------------------------
__device__ __forceinline__ float2 cmul(float2 a, float2 b) {
    return make_float2(a.x * b.x - a.y * b.y, a.x * b.y + a.y * b.x);
}
__device__ __forceinline__ float2 cadd(float2 a, float2 b) { return make_float2(a.x + b.x, a.y + b.y); }
__device__ __forceinline__ float2 csub(float2 a, float2 b) { return make_float2(a.x - b.x, a.y - b.y); }

// multiply by -i (forward, INV=0) or +i (inverse, INV=1)
template <int INV>
__device__ __forceinline__ float2 rot90(float2 a) {
    return INV ? make_float2(-a.y, a.x) : make_float2(a.y, -a.x);
}

// Natural-order 8-point DFT (DIT). Input v[n] time order, output v[k] freq order.
template <int INV>
__device__ __forceinline__ void fft8(float2 v[8]) {
    // FFT4 on evens (v0 v2 v4 v6)
    float2 t0 = cadd(v[0], v[4]), t1 = csub(v[0], v[4]);
    float2 t2 = cadd(v[2], v[6]), t3 = rot90<INV>(csub(v[2], v[6]));
    float2 E0 = cadd(t0, t2), E2 = csub(t0, t2);
    float2 E1 = cadd(t1, t3), E3 = csub(t1, t3);
    // FFT4 on odds (v1 v3 v5 v7)
    float2 u0 = cadd(v[1], v[5]), u1 = csub(v[1], v[5]);
    float2 u2 = cadd(v[3], v[7]), u3 = rot90<INV>(csub(v[3], v[7]));
    float2 O0 = cadd(u0, u2), O2 = csub(u0, u2);
    float2 O1 = cadd(u1, u3), O3 = csub(u1, u3);
    // twiddle odd outputs by w8^k
    const float r2 = 0.70710678118654752440f;
    float2 w1 = make_float2(r2, INV ? r2 : -r2);
    float2 w3 = make_float2(-r2, INV ? r2 : -r2);
    O1 = cmul(O1, w1);
    O2 = rot90<INV>(O2);
    O3 = cmul(O3, w3);
    v[0] = cadd(E0, O0); v[4] = csub(E0, O0);
    v[1] = cadd(E1, O1); v[5] = csub(E1, O1);
    v[2] = cadd(E2, O2); v[6] = csub(E2, O2);
    v[3] = cadd(E3, O3); v[7] = csub(E3, O3);
}

// Shared-memory padding: kills stage-0 store bank conflicts
#define PAD(i) ((i) + ((i) >> 3))

// 512-point Stockham FFT, radix-8, 3 stages, 64 threads (lane j = 0..63).
// Entry: v[r] = x[j + 64*r] (natural order).  Exit: v[r] = X[j + 64*r].
// S = per-FFT smem segment of >= PAD(511)+1 float2. Uses __syncthreads()
// (all 64-thread groups in the block must call in lockstep).
template <int INV>
__device__ __forceinline__ void fft512(float2 v[8], const float2* __restrict__ tw,
                                       float2* S, int j) {
    // ---- stage 0: Ns = 1 (no twiddle) ----
    fft8<INV>(v);
    __syncthreads();                               // callers' pending reads of S done
    #pragma unroll
    for (int r = 0; r < 8; r++) S[PAD(8 * j + r)] = v[r];
    __syncthreads();
    #pragma unroll
    for (int r = 0; r < 8; r++) v[r] = S[PAD(j + 64 * r)];
    // ---- stage 1: Ns = 8 ----
    {
        int jm = j & 7;
        #pragma unroll
        for (int r = 1; r < 8; r++) {
            float2 t = tw[(r * jm * 8) & 511];
            if (INV) t.y = -t.y;
            v[r] = cmul(v[r], t);
        }
        fft8<INV>(v);
    }
    __syncthreads();
    {
        int idxD = ((j >> 3) << 6) + (j & 7);
        #pragma unroll
        for (int r = 0; r < 8; r++) S[PAD(idxD + 8 * r)] = v[r];
    }
    __syncthreads();
    #pragma unroll
    for (int r = 0; r < 8; r++) v[r] = S[PAD(j + 64 * r)];
    // ---- stage 2: Ns = 64 ----
    {
        #pragma unroll
        for (int r = 1; r < 8; r++) {
            float2 t = tw[(r * j) & 511];
            if (INV) t.y = -t.y;
            v[r] = cmul(v[r], t);
        }
        fft8<INV>(v);
    }
    // NOTE: exits having just READ S; caller must __syncthreads() before writing S.
}

// ---------------------------------------------------------------------------
// Twiddle table (double-precision trig; accuracy for 11 chained passes)
// ---------------------------------------------------------------------------
__global__ void k_tw() {
    int i = threadIdx.x;
    double s, c;
    sincospi(-(double)i / 256.0, &s, &c);          // angle = -2*pi*i/512
    g_tw[i] = make_float2((float)c, (float)s);
}

// ---------------------------------------------------------------------------
// Propagation tables. MUST replicate the reference fp32 op chain bit-exactly:
//   fx    = i / float(8e-6 * 512)
//   kx    = float(2*pi) * fx                 (same for ky)
//   k     = float(2*pi) / wl
//   arg   = (k*k - kx*kx) - ky*ky            (strict rn, no FMA)
//   arg>=0: theta = sqrt_rn(arg) * z ; P = (cosf, sinf)(theta)
//   arg<0 : P = (expf(-sqrt_rn(-arg) * z), 0)
// Stored TRANSPOSED: slot [w][i][jj] holds value(a=jj /*FX idx*/, b=i /*FY idx*/),
// because (A-x)-y != (A-y)-x bitwise and the column pass needs coalesced reads
// along the FX index.
// ---------------------------------------------------------------------------
__device__ __forceinline__ float2 prop_val(float arg, float z) {
    if (arg >= 0.0f) {
        float th = __fmul_rn(__fsqrt_rn(arg), z);
        float s, c;
        sincosf(th, &s, &c);
        return make_float2(c, s);
    } else {
        float dec = __fmul_rn(__fsqrt_rn(-arg), z);
        return make_float2(expf(-dec), 0.0f);
    }
}

__global__ void k_prop() {
    int idx = blockIdx.x * 256 + threadIdx.x;
    if (idx >= NWL * IMG_ELEMS) return;
    int jj = idx & 511;            // FX index a
    int i  = (idx >> 9) & 511;     // FY index b
    int w  = idx >> 18;

    const float dn = (float)(8e-06 * 512.0);
    int ia = (jj < 256) ? jj : jj - 512;
    int ib = (i  < 256) ? i  : i  - 512;
    const float TWO_PI = (float)6.283185307179586;
    float fxa = __fdiv_rn((float)ia, dn);
    float fxb = __fdiv_rn((float)ib, dn);
    float kxa = __fmul_rn(TWO_PI, fxa);
    float kyb = __fmul_rn(TWO_PI, fxb);
    float wl = (w == 0) ? (float)5.32e-07 : ((w == 1) ? (float)6.33e-07 : (float)8.5e-07);
    float k  = __fdiv_rn(TWO_PI, wl);
    float arg = __fsub_rn(__fsub_rn(__fmul_rn(k, k), __fmul_rn(kxa, kxa)),
                          __fmul_rn(kyb, kyb));
    float2 pl = prop_val(arg, (float)0.03);
    float2 pd = prop_val(arg, (float)0.1);
    g_PLT[idx]  = pl;
    g_PLDT[idx] = cmul(pl, pd);
}

// ---------------------------------------------------------------------------
// Pass A: (x_real + i x_imag) * exp(i mask0)  -> row FFT -> g_bufA
// 256 threads = 4 rows/block, 64 lanes per row.
// ---------------------------------------------------------------------------
__global__ void k_rowA(const float* __restrict__ xr, const float* __restrict__ xi,
                       const float* __restrict__ mask0) {
    __shared__ float2 tw[512];
    __shared__ float2 seg[4 * 577];
    int tid = threadIdx.x;
    for (int i = tid; i < 512; i += 256) tw[i] = g_tw[i];
    int g = tid >> 6, j = tid & 63;
    int rowg = blockIdx.x * 4 + g;                 // global row id: img*512 + a
    int img = rowg >> 9, a = rowg & 511, w = img % 3;
    const float* mrow = mask0 + ((size_t)(w * H + a)) * H;
    size_t base = (size_t)rowg * H;

    float2 v[8];
    #pragma unroll
    for (int r = 0; r < 8; r++) {
        int col = j + (r << 6);
        float re = xr[base + col], im = xi[base + col];
        float m = mrow[col];
        float s, c;
        sincosf(m, &s, &c);
        v[r] = make_float2(re * c - im * s, re * s + im * c);
    }
    fft512<0>(v, tw, seg + g * 577, j);
    #pragma unroll
    for (int r = 0; r < 8; r++) g_bufA[base + j + (r << 6)] = v[r];
}

// ---------------------------------------------------------------------------
// Pass C: g_bufB -> row IFFT (x 1/512) -> * exp(i mask_l) -> row FFT -> g_bufA
// ---------------------------------------------------------------------------
__global__ void k_rowC(const float* __restrict__ mask) {
    __shared__ float2 tw[512];
    __shared__ float2 seg[4 * 577];
    int tid = threadIdx.x;
    for (int i = tid; i < 512; i += 256) tw[i] = g_tw[i];
    int g = tid >> 6, j = tid & 63;
    int rowg = blockIdx.x * 4 + g;
    int img = rowg >> 9, a = rowg & 511, w = img % 3;
    const float* mrow = mask + ((size_t)(w * H + a)) * H;
    size_t base = (size_t)rowg * H;
    float2* S = seg + g * 577;

    float2 v[8];
    #pragma unroll
    for (int r = 0; r < 8; r++) v[r] = g_bufB[base + j + (r << 6)];
    fft512<1>(v, tw, S, j);
    const float sc = 1.0f / 512.0f;
    #pragma unroll
    for (int r = 0; r < 8; r++) {
        int col = j + (r << 6);
        float m = mrow[col];
        float s, c;
        sincosf(m, &s, &c);
        float2 f = make_float2(v[r].x * sc, v[r].y * sc);
        v[r] = cmul(f, make_float2(c, s));
    }
    fft512<0>(v, tw, S, j);
    #pragma unroll
    for (int r = 0; r < 8; r++) g_bufA[base + j + (r << 6)] = v[r];
}

// ---------------------------------------------------------------------------
// Pass D: g_bufB -> row IFFT (x 1/512) -> d_out (interleaved re/im = float2)
// ---------------------------------------------------------------------------
__global__ void k_rowD(float2* __restrict__ out) {
    __shared__ float2 tw[512];
    __shared__ float2 seg[4 * 577];
    int tid = threadIdx.x;
    for (int i = tid; i < 512; i += 256) tw[i] = g_tw[i];
    int g = tid >> 6, j = tid & 63;
    int rowg = blockIdx.x * 4 + g;
    size_t base = (size_t)rowg * H;
    float2* S = seg + g * 577;

    float2 v[8];
    #pragma unroll
    for (int r = 0; r < 8; r++) v[r] = g_bufB[base + j + (r << 6)];
    fft512<1>(v, tw, S, j);
    const float sc = 1.0f / 512.0f;
    #pragma unroll
    for (int r = 0; r < 8; r++) {
        float2 t = v[r];
        t.x *= sc; t.y *= sc;
        out[base + j + (r << 6)] = t;
    }
}

// ---------------------------------------------------------------------------
// Pass B: g_bufA -> col FFT -> * P -> col IFFT (x 1/512) -> g_bufB
// 512 threads; 8 columns/block via padded smem tile; 72*64 blocks.
// ---------------------------------------------------------------------------
__global__ void k_col(int use_det) {
    __shared__ float2 tw[512];
    __shared__ float2 seg[8 * 577];
    int tid = threadIdx.x;
    tw[tid] = g_tw[tid];
    int img = blockIdx.x >> 6;                     // 64 col-tiles per image
    int colbase = (blockIdx.x & 63) << 3;
    int w = img % 3;

    const float2* src = g_bufA + (size_t)img * IMG_ELEMS;
    int c = tid & 7, r0 = tid >> 3;                // tile-load mapping
    #pragma unroll
    for (int it = 0; it < 8; it++) {
        int rr = r0 + (it << 6);
        seg[c * 577 + PAD(rr)] = src[(size_t)rr * H + colbase + c];
    }
    __syncthreads();

    int g = tid >> 6, j = tid & 63;                // FFT mapping: group g = column
    float2* S = seg + g * 577;
    float2 v[8];
    #pragma unroll
    for (int r = 0; r < 8; r++) v[r] = S[PAD(j + (r << 6))];

    fft512<0>(v, tw, S, j);

    // spectral multiply: element (a = j+64r, b = colbase+g) * P[w][a][b];
    // table stored transposed as [w][b][a] -> coalesced along a
    const float2* __restrict__ tab =
        (use_det ? g_PLDT : g_PLT) + ((size_t)(w * H + colbase + g)) * H;
    #pragma unroll
    for (int r = 0; r < 8; r++) v[r] = cmul(v[r], tab[j + (r << 6)]);

    fft512<1>(v, tw, S, j);

    __syncthreads();                               // everyone done reading S
    const float sc = 1.0f / 512.0f;
    #pragma unroll
    for (int r = 0; r < 8; r++) {
        float2 t = v[r];
        t.x *= sc; t.y *= sc;
        S[PAD(j + (r << 6))] = t;
    }
    __syncthreads();

    float2* dst = g_bufB + (size_t)img * IMG_ELEMS;
    #pragma unroll
    for (int it = 0; it < 8; it++) {
        int rr = r0 + (it << 6);
        dst[(size_t)rr * H + colbase + c] = seg[c * 577 + PAD(rr)];
    }
}

// ---------------------------------------------------------------------------
// Launch: 11 fused passes + 2 tiny table kernels. Graph-capturable (kernel
// launches only, default stream, no allocations, deterministic).
// ---------------------------------------------------------------------------
extern "C" void kernel_launch(void* const* d_in, const int* in_sizes, int n_in,
                              void* d_out, int out_size) {
    (void)in_sizes; (void)n_in; (void)out_size;
    const float* xr = (const float*)d_in[0];
    const float* xi = (const float*)d_in[1];
    const float* pm = (const float*)d_in[2];   // [5, 3, 512, 512]

    k_tw<<<1, 512>>>();
    k_prop<<<(NWL * IMG_ELEMS + 255) / 256, 256>>>();

    // input + mask0 + row FFT
    k_rowA<<<NIMG * H / 4, 256>>>(xr, xi, pm);

    for (int l = 0; l < NUM_LAYERS; l++) {
        // col FFT * P * col IFFT   (layer 4 folds in prop_det; the
        // intervening ifft2/fft2 pair of the reference is the identity)
        k_col<<<NIMG * 64, 512>>>((l == NUM_LAYERS - 1) ? 1 : 0);
        if (l < NUM_LAYERS - 1) {
            // row IFFT * exp(i mask_{l+1}) * row FFT
            k_rowC<<<NIMG * H / 4, 256>>>(pm + (size_t)(l + 1) * NWL * IMG_ELEMS);
        }
    }

    // final row IFFT -> output (re/im interleaved == float2)
    k_rowD<<<NIMG * H / 4, 256>>>((float2*)d_out);
}

// round 7
// speedup vs baseline: 1.1857x; 1.1857x over previous
#include <cuda_runtime.h>
#include <math.h>

// Problem constants
#define NIMG 72                 // BATCH(8) * NUM_MODES(3) * NUM_WL(3)
#define H 512
#define IMG_ELEMS (H * H)       // 262144
#define NWL 3
#define NUM_LAYERS 5

// ---------------------------------------------------------------------------
// Scratch (no allocations allowed -> __device__ globals)
// ---------------------------------------------------------------------------
__device__ float2 g_bufA[NIMG * IMG_ELEMS];   // ~151 MB
__device__ float2 g_bufB[NIMG * IMG_ELEMS];   // ~151 MB
__device__ float2 g_PLT [NWL * IMG_ELEMS];    // prop_layer, stored TRANSPOSED: [w][b][a]
__device__ float2 g_PLDT[NWL * IMG_ELEMS];    // prop_layer * prop_det, transposed
__device__ float2 g_tw[512];                  // forward twiddles exp(-2*pi*i*k/512)

// ---------------------------------------------------------------------------
// Complex helpers
// ---------------------------------------------------------------------------
__device__ __forceinline__ float2 cmul(float2 a, float2 b) {
    return make_float2(a.x * b.x - a.y * b.y, a.x * b.y + a.y * b.x);
}
__device__ __forceinline__ float2 cadd(float2 a, float2 b) { return make_float2(a.x + b.x, a.y + b.y); }
__device__ __forceinline__ float2 csub(float2 a, float2 b) { return make_float2(a.x - b.x, a.y - b.y); }

// multiply by -i (forward, INV=0) or +i (inverse, INV=1)
template <int INV>
__device__ __forceinline__ float2 rot90(float2 a) {
    return INV ? make_float2(-a.y, a.x) : make_float2(a.y, -a.x);
}

// Natural-order 8-point DFT (DIT). Input v[n] time order, output v[k] freq order.
template <int INV>
__device__ __forceinline__ void fft8(float2 v[8]) {
    float2 t0 = cadd(v[0], v[4]), t1 = csub(v[0], v[4]);
    float2 t2 = cadd(v[2], v[6]), t3 = rot90<INV>(csub(v[2], v[6]));
    float2 E0 = cadd(t0, t2), E2 = csub(t0, t2);
    float2 E1 = cadd(t1, t3), E3 = csub(t1, t3);
    float2 u0 = cadd(v[1], v[5]), u1 = csub(v[1], v[5]);
    float2 u2 = cadd(v[3], v[7]), u3 = rot90<INV>(csub(v[3], v[7]));
    float2 O0 = cadd(u0, u2), O2 = csub(u0, u2);
    float2 O1 = cadd(u1, u3), O3 = csub(u1, u3);
    const float r2 = 0.70710678118654752440f;
    float2 w1 = make_float2(r2, INV ? r2 : -r2);
    float2 w3 = make_float2(-r2, INV ? r2 : -r2);
    O1 = cmul(O1, w1);
    O2 = rot90<INV>(O2);
    O3 = cmul(O3, w3);
    v[0] = cadd(E0, O0); v[4] = csub(E0, O0);
    v[1] = cadd(E1, O1); v[5] = csub(E1, O1);
    v[2] = cadd(E2, O2); v[6] = csub(E2, O2);
    v[3] = cadd(E3, O3); v[7] = csub(E3, O3);
}

// Shared-memory padding: kills stage-0 store bank conflicts
#define PAD(i) ((i) + ((i) >> 3))

// 512-point Stockham FFT, radix-8, 3 stages, 64 threads (lane j = 0..63).
// Entry: v[r] = x[j + 64*r] (natural order).  Exit: v[r] = X[j + 64*r].
template <int INV>
__device__ __forceinline__ void fft512(float2 v[8], const float2* __restrict__ tw,
                                       float2* S, int j) {
    // ---- stage 0: Ns = 1 (no twiddle) ----
    fft8<INV>(v);
    __syncthreads();
    #pragma unroll
    for (int r = 0; r < 8; r++) S[PAD(8 * j + r)] = v[r];
    __syncthreads();
    #pragma unroll
    for (int r = 0; r < 8; r++) v[r] = S[PAD(j + 64 * r)];
    // ---- stage 1: Ns = 8 ----
    {
        int jm = j & 7;
        #pragma unroll
        for (int r = 1; r < 8; r++) {
            float2 t = tw[(r * jm * 8) & 511];
            if (INV) t.y = -t.y;
            v[r] = cmul(v[r], t);
        }
        fft8<INV>(v);
    }
    __syncthreads();
    {
        int idxD = ((j >> 3) << 6) + (j & 7);
        #pragma unroll
        for (int r = 0; r < 8; r++) S[PAD(idxD + 8 * r)] = v[r];
    }
    __syncthreads();
    #pragma unroll
    for (int r = 0; r < 8; r++) v[r] = S[PAD(j + 64 * r)];
    // ---- stage 2: Ns = 64 ----
    {
        #pragma unroll
        for (int r = 1; r < 8; r++) {
            float2 t = tw[(r * j) & 511];
            if (INV) t.y = -t.y;
            v[r] = cmul(v[r], t);
        }
        fft8<INV>(v);
    }
    // exits having just READ S; caller must __syncthreads() before writing S.
}

// ---------------------------------------------------------------------------
// Twiddle table (double-precision trig; accuracy for 11 chained passes)
// ---------------------------------------------------------------------------
__global__ void k_tw() {
    int i = threadIdx.x;
    double s, c;
    sincospi(-(double)i / 256.0, &s, &c);          // angle = -2*pi*i/512
    g_tw[i] = make_float2((float)c, (float)s);
}

// ---------------------------------------------------------------------------
// Propagation tables — bit-exact replica of the reference fp32 op chain.
// Stored TRANSPOSED [w][b][a] so the column pass reads coalesced along a.
// ---------------------------------------------------------------------------
__device__ __forceinline__ float2 prop_val(float arg, float z) {
    if (arg >= 0.0f) {
        float th = __fmul_rn(__fsqrt_rn(arg), z);
        float s, c;
        sincosf(th, &s, &c);
        return make_float2(c, s);
    } else {
        float dec = __fmul_rn(__fsqrt_rn(-arg), z);
        return make_float2(expf(-dec), 0.0f);
    }
}

__global__ void k_prop() {
    int idx = blockIdx.x * 256 + threadIdx.x;
    if (idx >= NWL * IMG_ELEMS) return;
    int jj = idx & 511;            // FX index a
    int i  = (idx >> 9) & 511;     // FY index b
    int w  = idx >> 18;

    const float dn = (float)(8e-06 * 512.0);
    int ia = (jj < 256) ? jj : jj - 512;
    int ib = (i  < 256) ? i  : i  - 512;
    const float TWO_PI = (float)6.283185307179586;
    float fxa = __fdiv_rn((float)ia, dn);
    float fxb = __fdiv_rn((float)ib, dn);
    float kxa = __fmul_rn(TWO_PI, fxa);
    float kyb = __fmul_rn(TWO_PI, fxb);
    float wl = (w == 0) ? (float)5.32e-07 : ((w == 1) ? (float)6.33e-07 : (float)8.5e-07);
    float k  = __fdiv_rn(TWO_PI, wl);
    float arg = __fsub_rn(__fsub_rn(__fmul_rn(k, k), __fmul_rn(kxa, kxa)),
                          __fmul_rn(kyb, kyb));
    float2 pl = prop_val(arg, (float)0.03);
    float2 pd = prop_val(arg, (float)0.1);
    g_PLT[idx]  = pl;
    g_PLDT[idx] = cmul(pl, pd);
}

// ---------------------------------------------------------------------------
// Pass A: (x_real + i x_imag) * exp(i mask0)  -> row FFT -> g_bufA
// 256 threads = 4 rows/block. launch_bounds(256,4): 64 regs -> 4 blocks/SM.
// ---------------------------------------------------------------------------
__global__ void __launch_bounds__(256, 4)
k_rowA(const float* __restrict__ xr, const float* __restrict__ xi,
       const float* __restrict__ mask0) {
    __shared__ float2 tw[512];
    __shared__ float2 seg[4 * 577];
    int tid = threadIdx.x;
    for (int i = tid; i < 512; i += 256) tw[i] = g_tw[i];
    int g = tid >> 6, j = tid & 63;
    int rowg = blockIdx.x * 4 + g;                 // global row id: img*512 + a
    int img = rowg >> 9, a = rowg & 511, w = img % 3;
    const float* mrow = mask0 + ((size_t)(w * H + a)) * H;
    size_t base = (size_t)rowg * H;

    float2 v[8];
    #pragma unroll
    for (int r = 0; r < 8; r++) {
        int col = j + (r << 6);
        float re = xr[base + col], im = xi[base + col];
        float m = mrow[col];
        float s, c;
        sincosf(m, &s, &c);
        v[r] = make_float2(re * c - im * s, re * s + im * c);
    }
    fft512<0>(v, tw, seg + g * 577, j);
    #pragma unroll
    for (int r = 0; r < 8; r++) g_bufA[base + j + (r << 6)] = v[r];
}

// ---------------------------------------------------------------------------
// Pass C: g_bufB -> row IFFT (x 1/512) -> * exp(i mask_l) -> row FFT -> g_bufA
// ---------------------------------------------------------------------------
__global__ void __launch_bounds__(256, 4)
k_rowC(const float* __restrict__ mask) {
    __shared__ float2 tw[512];
    __shared__ float2 seg[4 * 577];
    int tid = threadIdx.x;
    for (int i = tid; i < 512; i += 256) tw[i] = g_tw[i];
    int g = tid >> 6, j = tid & 63;
    int rowg = blockIdx.x * 4 + g;
    int img = rowg >> 9, a = rowg & 511, w = img % 3;
    const float* mrow = mask + ((size_t)(w * H + a)) * H;
    size_t base = (size_t)rowg * H;
    float2* S = seg + g * 577;

    float2 v[8];
    #pragma unroll
    for (int r = 0; r < 8; r++) v[r] = g_bufB[base + j + (r << 6)];
    fft512<1>(v, tw, S, j);
    const float sc = 1.0f / 512.0f;
    #pragma unroll
    for (int r = 0; r < 8; r++) {
        int col = j + (r << 6);
        float m = mrow[col];
        float s, c;
        sincosf(m, &s, &c);
        float2 f = make_float2(v[r].x * sc, v[r].y * sc);
        v[r] = cmul(f, make_float2(c, s));
    }
    fft512<0>(v, tw, S, j);
    #pragma unroll
    for (int r = 0; r < 8; r++) g_bufA[base + j + (r << 6)] = v[r];
}

// ---------------------------------------------------------------------------
// Pass D: g_bufB -> row IFFT (x 1/512) -> d_out (interleaved re/im = float2)
// ---------------------------------------------------------------------------
__global__ void __launch_bounds__(256, 4)
k_rowD(float2* __restrict__ out) {
    __shared__ float2 tw[512];
    __shared__ float2 seg[4 * 577];
    int tid = threadIdx.x;
    for (int i = tid; i < 512; i += 256) tw[i] = g_tw[i];
    int g = tid >> 6, j = tid & 63;
    int rowg = blockIdx.x * 4 + g;
    size_t base = (size_t)rowg * H;
    float2* S = seg + g * 577;

    float2 v[8];
    #pragma unroll
    for (int r = 0; r < 8; r++) v[r] = g_bufB[base + j + (r << 6)];
    fft512<1>(v, tw, S, j);
    const float sc = 1.0f / 512.0f;
    #pragma unroll
    for (int r = 0; r < 8; r++) {
        float2 t = v[r];
        t.x *= sc; t.y *= sc;
        out[base + j + (r << 6)] = t;
    }
}

// ---------------------------------------------------------------------------
// Pass B: g_bufA -> col FFT -> * P -> col IFFT (x 1/512) -> g_bufB
// 512 threads; 8 columns/block via padded smem tile; 72*64 blocks.
// launch_bounds(512,2): caps regs at 64 -> 2 blocks/SM (smem 41KB*2 fits),
// doubling occupancy 25% -> 50% so barriers overlap with the peer block.
// ---------------------------------------------------------------------------
__global__ void __launch_bounds__(512, 2)
k_col(int use_det) {
    __shared__ float2 tw[512];
    __shared__ float2 seg[8 * 577];
    int tid = threadIdx.x;
    tw[tid] = g_tw[tid];
    int img = blockIdx.x >> 6;                     // 64 col-tiles per image
    int colbase = (blockIdx.x & 63) << 3;
    int w = img % 3;

    const float2* src = g_bufA + (size_t)img * IMG_ELEMS;
    int c = tid & 7, r0 = tid >> 3;                // tile-load mapping
    #pragma unroll
    for (int it = 0; it < 8; it++) {
        int rr = r0 + (it << 6);
        seg[c * 577 + PAD(rr)] = src[(size_t)rr * H + colbase + c];
    }
    __syncthreads();

    int g = tid >> 6, j = tid & 63;                // FFT mapping: group g = column
    float2* S = seg + g * 577;
    float2 v[8];
    #pragma unroll
    for (int r = 0; r < 8; r++) v[r] = S[PAD(j + (r << 6))];

    fft512<0>(v, tw, S, j);

    // spectral multiply: element (a = j+64r, b = colbase+g) * P[w][a][b];
    // table stored transposed as [w][b][a] -> coalesced along a
    const float2* __restrict__ tab =
        (use_det ? g_PLDT : g_PLT) + ((size_t)(w * H + colbase + g)) * H;
    #pragma unroll
    for (int r = 0; r < 8; r++) v[r] = cmul(v[r], tab[j + (r << 6)]);

    fft512<1>(v, tw, S, j);

    __syncthreads();                               // everyone done reading S
    const float sc = 1.0f / 512.0f;
    #pragma unroll
    for (int r = 0; r < 8; r++) {
        float2 t = v[r];
        t.x *= sc; t.y *= sc;
        S[PAD(j + (r << 6))] = t;
    }
    __syncthreads();

    float2* dst = g_bufB + (size_t)img * IMG_ELEMS;
    #pragma unroll
    for (int it = 0; it < 8; it++) {
        int rr = r0 + (it << 6);
        dst[(size_t)rr * H + colbase + c] = seg[c * 577 + PAD(rr)];
    }
}

// ---------------------------------------------------------------------------
// Launch: 11 fused passes + 2 tiny table kernels. Graph-capturable.
// ---------------------------------------------------------------------------
extern "C" void kernel_launch(void* const* d_in, const int* in_sizes, int n_in,
                              void* d_out, int out_size) {
    (void)in_sizes; (void)n_in; (void)out_size;
    const float* xr = (const float*)d_in[0];
    const float* xi = (const float*)d_in[1];
    const float* pm = (const float*)d_in[2];   // [5, 3, 512, 512]

    k_tw<<<1, 512>>>();
    k_prop<<<(NWL * IMG_ELEMS + 255) / 256, 256>>>();

    // input + mask0 + row FFT
    k_rowA<<<NIMG * H / 4, 256>>>(xr, xi, pm);

    for (int l = 0; l < NUM_LAYERS; l++) {
        // col FFT * P * col IFFT   (layer 4 folds in prop_det; the
        // intervening ifft2/fft2 pair of the reference is the identity)
        k_col<<<NIMG * 64, 512>>>((l == NUM_LAYERS - 1) ? 1 : 0);
        if (l < NUM_LAYERS - 1) {
            // row IFFT * exp(i mask_{l+1}) * row FFT
            k_rowC<<<NIMG * H / 4, 256>>>(pm + (size_t)(l + 1) * NWL * IMG_ELEMS);
        }
    }

    // final row IFFT -> output (re/im interleaved == float2)
    k_rowD<<<NIMG * H / 4, 256>>>((float2*)d_out);
}

// round 9
// speedup vs baseline: 1.6866x; 1.4225x over previous
#include <cuda_runtime.h>
#include <math.h>

// Problem constants
#define NIMG 72                 // BATCH(8) * NUM_MODES(3) * NUM_WL(3)
#define H 512
#define IMG_ELEMS (H * H)       // 262144
#define NWL 3
#define NUM_LAYERS 5

// ---------------------------------------------------------------------------
// Scratch (no allocations allowed -> __device__ globals)
// ---------------------------------------------------------------------------
__device__ float2 g_bufA[NIMG * IMG_ELEMS];   // ~151 MB
__device__ float2 g_bufB[NIMG * IMG_ELEMS];   // ~151 MB
__device__ float2 g_PLT [NWL * IMG_ELEMS];    // prop_layer * (1/512), TRANSPOSED [w][b][a]
__device__ float2 g_PLDT[NWL * IMG_ELEMS];    // prop_layer*prop_det*(1/512), transposed

// ---------------------------------------------------------------------------
// Complex helpers
// ---------------------------------------------------------------------------
__device__ __forceinline__ float2 cmul(float2 a, float2 b) {
    return make_float2(a.x * b.x - a.y * b.y, a.x * b.y + a.y * b.x);
}
__device__ __forceinline__ float2 cadd(float2 a, float2 b) { return make_float2(a.x + b.x, a.y + b.y); }
__device__ __forceinline__ float2 csub(float2 a, float2 b) { return make_float2(a.x - b.x, a.y - b.y); }

// multiply by -i (forward, INV=0) or +i (inverse, INV=1)
template <int INV>
__device__ __forceinline__ float2 rot90(float2 a) {
    return INV ? make_float2(-a.y, a.x) : make_float2(a.y, -a.x);
}

// Group-local barrier: 2 warps (64 threads) of one FFT group. Named HW
// barrier ids 1..8 (id 0 belongs to __syncthreads). Lets independent FFT
// groups in a block slide past each other instead of coupling all warps.
__device__ __forceinline__ void bar64(int id) {
    asm volatile("bar.sync %0, 64;" :: "r"(id) : "memory");
}

// Natural-order 8-point DFT (DIT). Input v[n] time order, output v[k] freq order.
template <int INV>
__device__ __forceinline__ void fft8(float2 v[8]) {
    float2 t0 = cadd(v[0], v[4]), t1 = csub(v[0], v[4]);
    float2 t2 = cadd(v[2], v[6]), t3 = rot90<INV>(csub(v[2], v[6]));
    float2 E0 = cadd(t0, t2), E2 = csub(t0, t2);
    float2 E1 = cadd(t1, t3), E3 = csub(t1, t3);
    float2 u0 = cadd(v[1], v[5]), u1 = csub(v[1], v[5]);
    float2 u2 = cadd(v[3], v[7]), u3 = rot90<INV>(csub(v[3], v[7]));
    float2 O0 = cadd(u0, u2), O2 = csub(u0, u2);
    float2 O1 = cadd(u1, u3), O3 = csub(u1, u3);
    const float r2 = 0.70710678118654752440f;
    float2 w1 = make_float2(r2, INV ? r2 : -r2);
    float2 w3 = make_float2(-r2, INV ? r2 : -r2);
    O1 = cmul(O1, w1);
    O2 = rot90<INV>(O2);
    O3 = cmul(O3, w3);
    v[0] = cadd(E0, O0); v[4] = csub(E0, O0);
    v[1] = cadd(E1, O1); v[5] = csub(E1, O1);
    v[2] = cadd(E2, O2); v[6] = csub(E2, O2);
    v[3] = cadd(E3, O3); v[7] = csub(E3, O3);
}

// Shared-memory padding: kills stage-0 store bank conflicts
#define PAD(i) ((i) + ((i) >> 3))

// 512-point Stockham FFT, radix-8, 3 stages, 64 threads (lane j = 0..63).
// Entry: v[r] = x[j + 64*r] (natural order).  Exit: v[r] = X[j + 64*r].
// Twiddles are generated arithmetically (1 sincosf + cmul recurrence per
// stage) instead of a shared table: removes 28 heavily bank-conflicted smem
// loads per thread per call. Exchange barriers are group-local (bar.sync bid,64).
template <int INV>
__device__ __forceinline__ void fft512(float2 v[8], float2* S, int j, int bid) {
    // ---- stage 0: Ns = 1 (no twiddle) ----
    fft8<INV>(v);
    bar64(bid);                                    // group's pending reads of S done
    #pragma unroll
    for (int r = 0; r < 8; r++) S[PAD(8 * j + r)] = v[r];
    bar64(bid);
    #pragma unroll
    for (int r = 0; r < 8; r++) v[r] = S[PAD(j + 64 * r)];
    // ---- stage 1: Ns = 8, twiddle w1^r, w1 = exp(-+2*pi*i*(j&7)/64) ----
    {
        float s, c;
        sincosf((INV ? 0.098174770424681035f : -0.098174770424681035f) * (float)(j & 7), &s, &c);
        float2 w = make_float2(c, s), t = w;
        #pragma unroll
        for (int r = 1; r < 8; r++) { v[r] = cmul(v[r], t); t = cmul(t, w); }
        fft8<INV>(v);
    }
    bar64(bid);
    {
        int idxD = ((j >> 3) << 6) + (j & 7);
        #pragma unroll
        for (int r = 0; r < 8; r++) S[PAD(idxD + 8 * r)] = v[r];
    }
    bar64(bid);
    #pragma unroll
    for (int r = 0; r < 8; r++) v[r] = S[PAD(j + 64 * r)];
    // ---- stage 2: Ns = 64, twiddle w^r, w = exp(-+2*pi*i*j/512) ----
    {
        float s, c;
        sincosf((INV ? 0.012271846303085130f : -0.012271846303085130f) * (float)j, &s, &c);
        float2 w = make_float2(c, s), t = w;
        #pragma unroll
        for (int r = 1; r < 8; r++) { v[r] = cmul(v[r], t); t = cmul(t, w); }
        fft8<INV>(v);
    }
    // exits having just READ S; caller must barrier before writing S.
}

// ---------------------------------------------------------------------------
// Propagation tables — bit-exact replica of the reference fp32 op chain.
// Stored TRANSPOSED [w][b][a] so the column pass reads coalesced along a.
// Tables are pre-scaled by 1/512 (the column inverse-FFT normalization),
// so k_col needs no separate scaling pass.
// ---------------------------------------------------------------------------
__device__ __forceinline__ float2 prop_val(float arg, float z) {
    if (arg >= 0.0f) {
        float th = __fmul_rn(__fsqrt_rn(arg), z);
        float s, c;
        sincosf(th, &s, &c);
        return make_float2(c, s);
    } else {
        float dec = __fmul_rn(__fsqrt_rn(-arg), z);
        return make_float2(expf(-dec), 0.0f);
    }
}

__global__ void k_prop() {
    int idx = blockIdx.x * 256 + threadIdx.x;
    if (idx >= NWL * IMG_ELEMS) return;
    int jj = idx & 511;            // FX index a
    int i  = (idx >> 9) & 511;     // FY index b
    int w  = idx >> 18;

    const float dn = (float)(8e-06 * 512.0);
    int ia = (jj < 256) ? jj : jj - 512;
    int ib = (i  < 256) ? i  : i  - 512;
    const float TWO_PI = (float)6.283185307179586;
    float fxa = __fdiv_rn((float)ia, dn);
    float fxb = __fdiv_rn((float)ib, dn);
    float kxa = __fmul_rn(TWO_PI, fxa);
    float kyb = __fmul_rn(TWO_PI, fxb);
    float wl = (w == 0) ? (float)5.32e-07 : ((w == 1) ? (float)6.33e-07 : (float)8.5e-07);
    float k  = __fdiv_rn(TWO_PI, wl);
    float arg = __fsub_rn(__fsub_rn(__fmul_rn(k, k), __fmul_rn(kxa, kxa)),
                          __fmul_rn(kyb, kyb));
    float2 pl = prop_val(arg, (float)0.03);
    float2 pd = prop_val(arg, (float)0.1);
    const float sc = 1.0f / 512.0f;
    float2 pld = cmul(pl, pd);
    g_PLT[idx]  = make_float2(pl.x * sc,  pl.y * sc);
    g_PLDT[idx] = make_float2(pld.x * sc, pld.y * sc);
}

// ---------------------------------------------------------------------------
// Pass A: (x_real + i x_imag) * exp(i mask0)  -> row FFT -> g_bufA
// 256 threads = 4 rows/block (groups use named barriers; no __syncthreads).
// ---------------------------------------------------------------------------
__global__ void __launch_bounds__(256, 4)
k_rowA(const float* __restrict__ xr, const float* __restrict__ xi,
       const float* __restrict__ mask0) {
    __shared__ float2 seg[4 * 577];
    int tid = threadIdx.x;
    int g = tid >> 6, j = tid & 63;
    int rowg = blockIdx.x * 4 + g;                 // global row id: img*512 + a
    int img = rowg >> 9, a = rowg & 511, w = img % 3;
    const float* mrow = mask0 + ((size_t)(w * H + a)) * H;
    size_t base = (size_t)rowg * H;

    float2 v[8];
    #pragma unroll
    for (int r = 0; r < 8; r++) {
        int col = j + (r << 6);
        float re = xr[base + col], im = xi[base + col];
        float m = mrow[col];
        float s, c;
        sincosf(m, &s, &c);
        v[r] = make_float2(re * c - im * s, re * s + im * c);
    }
    fft512<0>(v, seg + g * 577, j, g + 1);
    #pragma unroll
    for (int r = 0; r < 8; r++) g_bufA[base + j + (r << 6)] = v[r];
}

// ---------------------------------------------------------------------------
// Pass C: g_bufB -> row IFFT -> * (1/512)*exp(i mask_l) -> row FFT -> g_bufA
// ---------------------------------------------------------------------------
__global__ void __launch_bounds__(256, 4)
k_rowC(const float* __restrict__ mask) {
    __shared__ float2 seg[4 * 577];
    int tid = threadIdx.x;
    int g = tid >> 6, j = tid & 63;
    int rowg = blockIdx.x * 4 + g;
    int img = rowg >> 9, a = rowg & 511, w = img % 3;
    const float* mrow = mask + ((size_t)(w * H + a)) * H;
    size_t base = (size_t)rowg * H;
    float2* S = seg + g * 577;

    float2 v[8];
    #pragma unroll
    for (int r = 0; r < 8; r++) v[r] = g_bufB[base + j + (r << 6)];
    fft512<1>(v, S, j, g + 1);
    const float sc = 1.0f / 512.0f;
    #pragma unroll
    for (int r = 0; r < 8; r++) {
        int col = j + (r << 6);
        float m = mrow[col];
        float s, c;
        sincosf(m, &s, &c);
        v[r] = cmul(v[r], make_float2(c * sc, s * sc));   // ifft scale folded in
    }
    fft512<0>(v, S, j, g + 1);
    #pragma unroll
    for (int r = 0; r < 8; r++) g_bufA[base + j + (r << 6)] = v[r];
}

// ---------------------------------------------------------------------------
// Pass D: g_bufB -> row IFFT (x 1/512) -> d_out (interleaved re/im = float2)
// ---------------------------------------------------------------------------
__global__ void __launch_bounds__(256, 4)
k_rowD(float2* __restrict__ out) {
    __shared__ float2 seg[4 * 577];
    int tid = threadIdx.x;
    int g = tid >> 6, j = tid & 63;
    int rowg = blockIdx.x * 4 + g;
    size_t base = (size_t)rowg * H;

    float2 v[8];
    #pragma unroll
    for (int r = 0; r < 8; r++) v[r] = g_bufB[base + j + (r << 6)];
    fft512<1>(v, seg + g * 577, j, g + 1);
    const float sc = 1.0f / 512.0f;
    #pragma unroll
    for (int r = 0; r < 8; r++) {
        float2 t = v[r];
        t.x *= sc; t.y *= sc;
        out[base + j + (r << 6)] = t;
    }
}

// ---------------------------------------------------------------------------
// Pass B: g_bufA -> col FFT -> * P(pre-scaled) -> col IFFT -> g_bufB
// 512 threads; 8 columns/block via padded smem tile; 72*64 blocks.
// launch_bounds(512,2): 64 regs -> 2 blocks/SM (RF exactly full).
// FFT groups use named barriers 1..8; __syncthreads only at the two
// cross-group transpose phases.
// ---------------------------------------------------------------------------
__global__ void __launch_bounds__(512, 2)
k_col(int use_det) {
    __shared__ float2 seg[8 * 577];
    int tid = threadIdx.x;
    int img = blockIdx.x >> 6;                     // 64 col-tiles per image
    int colbase = (blockIdx.x & 63) << 3;
    int w = img % 3;

    const float2* src = g_bufA + (size_t)img * IMG_ELEMS;
    int c = tid & 7, r0 = tid >> 3;                // tile-load mapping
    #pragma unroll
    for (int it = 0; it < 8; it++) {
        int rr = r0 + (it << 6);
        seg[c * 577 + PAD(rr)] = src[(size_t)rr * H + colbase + c];
    }
    __syncthreads();

    int g = tid >> 6, j = tid & 63;                // FFT mapping: group g = column
    float2* S = seg + g * 577;
    float2 v[8];
    #pragma unroll
    for (int r = 0; r < 8; r++) v[r] = S[PAD(j + (r << 6))];

    fft512<0>(v, S, j, g + 1);

    // spectral multiply: element (a = j+64r, b = colbase+g) * P[w][a][b];
    // table stored transposed as [w][b][a] -> coalesced along a; pre-scaled 1/512
    const float2* __restrict__ tab =
        (use_det ? g_PLDT : g_PLT) + ((size_t)(w * H + colbase + g)) * H;
    #pragma unroll
    for (int r = 0; r < 8; r++) v[r] = cmul(v[r], tab[j + (r << 6)]);

    fft512<1>(v, S, j, g + 1);

    __syncthreads();                               // all groups done reading S
    #pragma unroll
    for (int r = 0; r < 8; r++) S[PAD(j + (r << 6))] = v[r];
    __syncthreads();

    float2* dst = g_bufB + (size_t)img * IMG_ELEMS;
    #pragma unroll
    for (int it = 0; it < 8; it++) {
        int rr = r0 + (it << 6);
        dst[(size_t)rr * H + colbase + c] = seg[c * 577 + PAD(rr)];
    }
}

// ---------------------------------------------------------------------------
// Launch: 11 fused passes + 1 tiny table kernel. Graph-capturable.
// ---------------------------------------------------------------------------
extern "C" void kernel_launch(void* const* d_in, const int* in_sizes, int n_in,
                              void* d_out, int out_size) {
    (void)in_sizes; (void)n_in; (void)out_size;
    const float* xr = (const float*)d_in[0];
    const float* xi = (const float*)d_in[1];
    const float* pm = (const float*)d_in[2];   // [5, 3, 512, 512]

    k_prop<<<(NWL * IMG_ELEMS + 255) / 256, 256>>>();

    // input + mask0 + row FFT
    k_rowA<<<NIMG * H / 4, 256>>>(xr, xi, pm);

    for (int l = 0; l < NUM_LAYERS; l++) {
        // col FFT * P * col IFFT   (layer 4 folds in prop_det; the
        // intervening ifft2/fft2 pair of the reference is the identity)
        k_col<<<NIMG * 64, 512>>>((l == NUM_LAYERS - 1) ? 1 : 0);
        if (l < NUM_LAYERS - 1) {
            // row IFFT * exp(i mask_{l+1}) * row FFT
            k_rowC<<<NIMG * H / 4, 256>>>(pm + (size_t)(l + 1) * NWL * IMG_ELEMS);
        }
    }

    // final row IFFT -> output (re/im interleaved == float2)
    k_rowD<<<NIMG * H / 4, 256>>>((float2*)d_out);
}